// round 1
// baseline (speedup 1.0000x reference)
#include <cuda_runtime.h>
#include <cuda_bf16.h>
#include <math.h>

// Problem constants (fixed by the dataset)
#define NNODES 100000
#define NEDGES 1600000
#define DIN 128
#define DH  128
#define DOUT 64

// ---------------- device scratch (no allocations allowed) ----------------
__device__ __align__(16) static float g_bufA[(size_t)NNODES * DH];   // aggregate buffer / m3
__device__ __align__(16) static float g_bufB[(size_t)NNODES * DH];   // layer output buffer
__device__ __align__(16) static float g_bufG[(size_t)NNODES * DOUT]; // g = h2 @ W3
__device__ static int   g_rowptr[NNODES + 1];
__device__ static int   g_cursor[NNODES + 1];
__device__ static int   g_colidx[NEDGES];
__device__ static int   g_outdeg[NNODES];
__device__ static int   g_indeg[NNODES];
__device__ static float g_norm_src[NNODES];
__device__ static float g_norm_dst[NNODES];
__device__ static int   g_blksums[256];

// ---------------- CSR build ----------------
__global__ void zero_deg_kernel(int n) {
    int i = blockIdx.x * blockDim.x + threadIdx.x;
    if (i < n) { g_outdeg[i] = 0; g_indeg[i] = 0; }
}

__global__ void deg_kernel(const int* __restrict__ src, const int* __restrict__ dst, int E) {
    int e = blockIdx.x * blockDim.x + threadIdx.x;
    if (e < E) {
        atomicAdd(&g_outdeg[src[e]], 1);
        atomicAdd(&g_indeg[dst[e]], 1);
    }
}

__global__ void norm_kernel(int n) {
    int i = blockIdx.x * blockDim.x + threadIdx.x;
    if (i < n) {
        int od = g_outdeg[i]; if (od < 1) od = 1;
        int id = g_indeg[i];  if (id < 1) id = 1;
        g_norm_src[i] = rsqrtf((float)od);
        g_norm_dst[i] = rsqrtf((float)id);
    }
}

// scan pass 1: per-block (1024 elems) exclusive scan of g_indeg -> g_rowptr, totals -> g_blksums
__global__ void scan1_kernel(int n) {
    __shared__ int warp_sums[8];
    int base = blockIdx.x * 1024;
    int t = threadIdx.x;
    int idx0 = base + t * 4;
    int v[4];
#pragma unroll
    for (int i = 0; i < 4; i++) { int idx = idx0 + i; v[i] = (idx < n) ? g_indeg[idx] : 0; }
    int s = v[0] + v[1] + v[2] + v[3];
    int lane = t & 31, wid = t >> 5;
    int ss = s;
#pragma unroll
    for (int o = 1; o < 32; o <<= 1) { int x = __shfl_up_sync(0xFFFFFFFFu, ss, o); if (lane >= o) ss += x; }
    if (lane == 31) warp_sums[wid] = ss;
    __syncthreads();
    if (wid == 0) {
        int w = (lane < 8) ? warp_sums[lane] : 0;
#pragma unroll
        for (int o = 1; o < 8; o <<= 1) { int x = __shfl_up_sync(0xFFFFFFFFu, w, o); if (lane >= o) w += x; }
        if (lane < 8) warp_sums[lane] = w;
    }
    __syncthreads();
    int excl = ss - s + ((wid > 0) ? warp_sums[wid - 1] : 0);
    int run = excl;
#pragma unroll
    for (int i = 0; i < 4; i++) { int idx = idx0 + i; if (idx < n) g_rowptr[idx] = run; run += v[i]; }
    if (t == 255) g_blksums[blockIdx.x] = warp_sums[7];
}

// scan pass 2: exclusive scan of block sums (nb <= 128), single block of 128 threads
__global__ void scan2_kernel(int nb) {
    __shared__ int ws[4];
    int t = threadIdx.x;
    int v = (t < nb) ? g_blksums[t] : 0;
    int lane = t & 31, wid = t >> 5;
    int s = v;
#pragma unroll
    for (int o = 1; o < 32; o <<= 1) { int x = __shfl_up_sync(0xFFFFFFFFu, s, o); if (lane >= o) s += x; }
    if (lane == 31) ws[wid] = s;
    __syncthreads();
    if (wid == 0) {
        int w = (lane < 4) ? ws[lane] : 0;
#pragma unroll
        for (int o = 1; o < 4; o <<= 1) { int x = __shfl_up_sync(0xFFFFFFFFu, w, o); if (lane >= o) w += x; }
        if (lane < 4) ws[lane] = w;
    }
    __syncthreads();
    int excl = s - v + ((wid > 0) ? ws[wid - 1] : 0);
    if (t < nb) g_blksums[t] = excl;
}

// scan pass 3: add block offsets, mirror to cursor, close row_ptr
__global__ void scan3_kernel(int n, int E) {
    int idx = blockIdx.x * blockDim.x + threadIdx.x;
    if (idx < n) {
        int v = g_rowptr[idx] + g_blksums[idx >> 10];
        g_rowptr[idx] = v;
        g_cursor[idx] = v;
    }
    if (idx == n) g_rowptr[n] = E;
}

__global__ void scatter_kernel(const int* __restrict__ src, const int* __restrict__ dst, int E) {
    int e = blockIdx.x * blockDim.x + threadIdx.x;
    if (e < E) {
        int d = dst[e];
        int p = atomicAdd(&g_cursor[d], 1);
        g_colidx[p] = src[e];
    }
}

// ---------------- SpMM: out[v] = norm_dst[v] * sum_{u in N_in(v)} (scale(u) * x[u]) ----------------
template<int D, bool SRCSCALE>
__global__ __launch_bounds__(256) void spmm_kernel(
    const float* __restrict__ x, const float* __restrict__ sscale,
    float* __restrict__ out, int n)
{
    int warp = (blockIdx.x * 256 + threadIdx.x) >> 5;
    int lane = threadIdx.x & 31;
    if (warp >= n) return;
    int beg = __ldg(&g_rowptr[warp]);
    int end = __ldg(&g_rowptr[warp + 1]);
    float dsc = __ldg(&g_norm_dst[warp]);

    if (D == 128) {
        const float4* xp = (const float4*)x;
        float4 a0 = {0.f,0.f,0.f,0.f}, a1 = {0.f,0.f,0.f,0.f};
        int e = beg;
        for (; e + 1 < end; e += 2) {
            int u0 = __ldg(&g_colidx[e]);
            int u1 = __ldg(&g_colidx[e + 1]);
            float s0 = SRCSCALE ? __ldg(&sscale[u0]) : 1.0f;
            float s1 = SRCSCALE ? __ldg(&sscale[u1]) : 1.0f;
            float4 v0 = __ldg(&xp[(size_t)u0 * 32 + lane]);
            float4 v1 = __ldg(&xp[(size_t)u1 * 32 + lane]);
            a0.x += s0 * v0.x; a0.y += s0 * v0.y; a0.z += s0 * v0.z; a0.w += s0 * v0.w;
            a1.x += s1 * v1.x; a1.y += s1 * v1.y; a1.z += s1 * v1.z; a1.w += s1 * v1.w;
        }
        if (e < end) {
            int u0 = __ldg(&g_colidx[e]);
            float s0 = SRCSCALE ? __ldg(&sscale[u0]) : 1.0f;
            float4 v0 = __ldg(&xp[(size_t)u0 * 32 + lane]);
            a0.x += s0 * v0.x; a0.y += s0 * v0.y; a0.z += s0 * v0.z; a0.w += s0 * v0.w;
        }
        float4 r;
        r.x = (a0.x + a1.x) * dsc; r.y = (a0.y + a1.y) * dsc;
        r.z = (a0.z + a1.z) * dsc; r.w = (a0.w + a1.w) * dsc;
        ((float4*)out)[(size_t)warp * 32 + lane] = r;
    } else { // D == 64
        const float2* xp = (const float2*)x;
        float2 a0 = {0.f,0.f}, a1 = {0.f,0.f};
        int e = beg;
        for (; e + 1 < end; e += 2) {
            int u0 = __ldg(&g_colidx[e]);
            int u1 = __ldg(&g_colidx[e + 1]);
            float s0 = SRCSCALE ? __ldg(&sscale[u0]) : 1.0f;
            float s1 = SRCSCALE ? __ldg(&sscale[u1]) : 1.0f;
            float2 v0 = __ldg(&xp[(size_t)u0 * 32 + lane]);
            float2 v1 = __ldg(&xp[(size_t)u1 * 32 + lane]);
            a0.x += s0 * v0.x; a0.y += s0 * v0.y;
            a1.x += s1 * v1.x; a1.y += s1 * v1.y;
        }
        if (e < end) {
            int u0 = __ldg(&g_colidx[e]);
            float s0 = SRCSCALE ? __ldg(&sscale[u0]) : 1.0f;
            float2 v0 = __ldg(&xp[(size_t)u0 * 32 + lane]);
            a0.x += s0 * v0.x; a0.y += s0 * v0.y;
        }
        float2 r;
        r.x = (a0.x + a1.x) * dsc; r.y = (a0.y + a1.y) * dsc;
        ((float2*)out)[(size_t)warp * 32 + lane] = r;
    }
}

// ---------------- GEMM: C[M x NC] = A[M x 128] @ W[128 x NC], optional fused epilogue ----------------
// EPI_RELU: C = relu(acc + bias) * rowscale[row]   (rowscale = norm_src, folded for the NEXT SpMM)
template<int NC, bool EPI_RELU>
__global__ __launch_bounds__(256) void gemm_kernel(
    const float* __restrict__ A, const float* __restrict__ W,
    const float* __restrict__ bias, const float* __restrict__ rowscale,
    float* __restrict__ C, int M)
{
    constexpr int BM = 128, BK = 8;
    constexpr int TN = NC / 16;           // 8 for NC=128, 4 for NC=64
    __shared__ __align__(16) float As[BK][BM];   // transposed A tile
    __shared__ __align__(16) float Bs[BK][NC];

    int t  = threadIdx.x;
    int m0 = blockIdx.x * BM;
    int tx = t % 16;                      // column group
    int ty = t / 16;                      // row group

    float acc[8][TN];
#pragma unroll
    for (int i = 0; i < 8; i++)
#pragma unroll
        for (int j = 0; j < TN; j++) acc[i][j] = 0.f;

    for (int k0 = 0; k0 < 128; k0 += BK) {
        // load A tile: 128 rows x 8 cols
        {
            int r  = t >> 1;
            int kk = (t & 1) * 4;
            int gm = m0 + r;
            float4 av = {0.f,0.f,0.f,0.f};
            if (gm < M) av = *(const float4*)&A[(size_t)gm * 128 + k0 + kk];
            As[kk + 0][r] = av.x; As[kk + 1][r] = av.y;
            As[kk + 2][r] = av.z; As[kk + 3][r] = av.w;
        }
        // load W tile: 8 x NC
        if (NC == 128) {
            int r = t >> 5; int c = (t & 31) * 4;
            *(float4*)&Bs[r][c] = *(const float4*)&W[(size_t)(k0 + r) * NC + c];
        } else {
            if (t < 128) {
                int r = t >> 4; int c = (t & 15) * 4;
                *(float4*)&Bs[r][c] = *(const float4*)&W[(size_t)(k0 + r) * NC + c];
            }
        }
        __syncthreads();
#pragma unroll
        for (int k = 0; k < BK; k++) {
            float a[8], b[TN];
            float4 a0 = *(const float4*)&As[k][ty * 8];
            float4 a1 = *(const float4*)&As[k][ty * 8 + 4];
            a[0]=a0.x; a[1]=a0.y; a[2]=a0.z; a[3]=a0.w;
            a[4]=a1.x; a[5]=a1.y; a[6]=a1.z; a[7]=a1.w;
            if (TN == 8) {
                float4 b0 = *(const float4*)&Bs[k][tx * 8];
                float4 b1 = *(const float4*)&Bs[k][tx * 8 + 4];
                b[0]=b0.x; b[1]=b0.y; b[2]=b0.z; b[3]=b0.w;
                b[4]=b1.x; b[5]=b1.y; b[6]=b1.z; b[7]=b1.w;
            } else {
                float4 b0 = *(const float4*)&Bs[k][tx * 4];
                b[0]=b0.x; b[1]=b0.y; b[2]=b0.z; b[3]=b0.w;
            }
#pragma unroll
            for (int i = 0; i < 8; i++)
#pragma unroll
                for (int j = 0; j < TN; j++) acc[i][j] += a[i] * b[j];
        }
        __syncthreads();
    }

    // epilogue (vectorized stores, TN consecutive columns)
#pragma unroll
    for (int i = 0; i < 8; i++) {
        int gm = m0 + ty * 8 + i;
        if (gm >= M) continue;
        float rs = 1.0f;
        if (EPI_RELU) rs = __ldg(&rowscale[gm]);
        float vals[TN];
#pragma unroll
        for (int j = 0; j < TN; j++) {
            float v = acc[i][j];
            if (EPI_RELU) {
                v += __ldg(&bias[tx * TN + j]);
                v = fmaxf(v, 0.f) * rs;
            }
            vals[j] = v;
        }
        float* cp = &C[(size_t)gm * NC + tx * TN];
        if (TN == 8) {
            ((float4*)cp)[0] = make_float4(vals[0], vals[1], vals[2], vals[3]);
            ((float4*)cp)[1] = make_float4(vals[4], vals[5], vals[6], vals[7]);
        } else {
            ((float4*)cp)[0] = make_float4(vals[0], vals[1], vals[2], vals[3]);
        }
    }
}

// ---------------- final: out = log_softmax(m3 + b3) over 64 cols ----------------
__global__ __launch_bounds__(256) void final_kernel(
    const float* __restrict__ m, const float* __restrict__ b3,
    float* __restrict__ out, int n)
{
    int row = (blockIdx.x * 256 + threadIdx.x) >> 5;
    int lane = threadIdx.x & 31;
    if (row >= n) return;
    float2 v = *(const float2*)&m[(size_t)row * 64 + lane * 2];
    float2 bb = *(const float2*)&b3[lane * 2];
    v.x += bb.x; v.y += bb.y;
    float mx = fmaxf(v.x, v.y);
#pragma unroll
    for (int o = 16; o > 0; o >>= 1) mx = fmaxf(mx, __shfl_xor_sync(0xFFFFFFFFu, mx, o));
    float e = __expf(v.x - mx) + __expf(v.y - mx);
#pragma unroll
    for (int o = 16; o > 0; o >>= 1) e += __shfl_xor_sync(0xFFFFFFFFu, e, o);
    float lse = logf(e) + mx;
    float2 r; r.x = v.x - lse; r.y = v.y - lse;
    *(float2*)&out[(size_t)row * 64 + lane * 2] = r;
}

// ---------------- launch ----------------
extern "C" void kernel_launch(void* const* d_in, const int* in_sizes, int n_in,
                              void* d_out, int out_size)
{
    const float* features = (const float*)d_in[0];
    const int*   src      = (const int*)  d_in[1];
    const int*   dst      = (const int*)  d_in[2];
    const float* W1       = (const float*)d_in[3];
    const float* b1       = (const float*)d_in[4];
    const float* W2       = (const float*)d_in[5];
    const float* b2       = (const float*)d_in[6];
    const float* W3       = (const float*)d_in[7];
    const float* b3       = (const float*)d_in[8];
    float* out = (float*)d_out;

    const int N = in_sizes[0] / DIN;   // 100000
    const int E = in_sizes[1];         // 1600000

    float* bufA; cudaGetSymbolAddress((void**)&bufA, g_bufA);
    float* bufB; cudaGetSymbolAddress((void**)&bufB, g_bufB);
    float* bufG; cudaGetSymbolAddress((void**)&bufG, g_bufG);
    float* nsrc; cudaGetSymbolAddress((void**)&nsrc, g_norm_src);

    // ---- CSR build (per launch; graph-capturable, deterministic up to atomic order) ----
    zero_deg_kernel<<<(N + 255) / 256, 256>>>(N);
    deg_kernel<<<(E + 255) / 256, 256>>>(src, dst, E);
    norm_kernel<<<(N + 255) / 256, 256>>>(N);
    int nblk = (N + 1023) / 1024;
    scan1_kernel<<<nblk, 256>>>(N);
    scan2_kernel<<<1, 128>>>(nblk);
    scan3_kernel<<<(N + 1 + 255) / 256, 256>>>(N, E);
    scatter_kernel<<<(E + 255) / 256, 256>>>(src, dst, E);

    const int spmm_blocks = (N * 32 + 255) / 256;   // warp per node
    const int gemm_blocks = (N + 127) / 128;

    // ---- layer 1: aggregate(features * ns) * nd -> A ; B = relu(A@W1+b1)*ns ----
    spmm_kernel<128, true ><<<spmm_blocks, 256>>>(features, nsrc, bufA, N);
    gemm_kernel<128, true ><<<gemm_blocks, 256>>>(bufA, W1, b1, nsrc, bufB, N);

    // ---- layer 2: aggregate(B) * nd -> A ; B = relu(A@W2+b2)*ns ----
    spmm_kernel<128, false><<<spmm_blocks, 256>>>(bufB, nullptr, bufA, N);
    gemm_kernel<128, true ><<<gemm_blocks, 256>>>(bufA, W2, b2, nsrc, bufB, N);

    // ---- layer 3 (W-first): G = B@W3 ; A[:, :64] = aggregate(G) * nd ; out = log_softmax(A + b3) ----
    gemm_kernel<64, false><<<gemm_blocks, 256>>>(bufB, W3, nullptr, nullptr, bufG, N);
    spmm_kernel<64, false><<<spmm_blocks, 256>>>(bufG, nullptr, bufA, N);
    final_kernel<<<(N * 32 + 255) / 256, 256>>>(bufA, b3, out, N);
}